// round 16
// baseline (speedup 1.0000x reference)
#include <cuda_runtime.h>
#include <cuda_fp16.h>
#include <math.h>

// PixelCNN fused forward.
// R16 = R15 + conv1 load balance: 1188 half-pixel tasks (8 oc each) over 256
//       threads (imbalance 1.29x -> 1.08x). One swizzled STS.128 per task.
//   conv1 scalar FFMA2 -> A = fp16(relu(h1));
//   conv2 via mma.m16n8k16: A*Bh + A*Bl (2-term split, rel_err 9.6e-6);
//   XOR 16B-chunk swizzle on A. smem 28KB, 5 CTAs/SM.

#define IMG_H 64
#define IMG_W 64
#define NCH   16
#define TH    8
#define XR    (TH + 4)
#define XC    (IMG_W + 8)
#define AROWS 596          // 9*66 = 594 used + 2 pad

typedef unsigned long long u64;

struct PackedW {
    ulonglong2 w1t[24][4];    // [tap][ocgroup] fp32 pairs
    ulonglong2 w2[16][5][4];  // [ic][tap][ocgroup] fp32
    u64   b1[8];
    u64   b2[8];
    float w3[16];
    float b3;
    float pad[3];
};

__device__   PackedW g_w;
__constant__ PackedW c_w;

__device__ __forceinline__ u64 ffma2(u64 a, u64 b, u64 c) {
    u64 d;
    asm("fma.rn.f32x2 %0, %1, %2, %3;" : "=l"(d) : "l"(a), "l"(b), "l"(c));
    return d;
}
__device__ __forceinline__ u64 dup2(float x) {
    u64 d;
    asm("mov.b64 %0, {%1, %1};" : "=l"(d) : "f"(x));
    return d;
}
__device__ __forceinline__ float2 unpack2(u64 v) {
    float2 r;
    asm("mov.b64 {%0, %1}, %2;" : "=f"(r.x), "=f"(r.y) : "l"(v));
    return r;
}
__device__ __forceinline__ unsigned smem_u32(const void* p) {
    unsigned a;
    asm("{ .reg .u64 t; cvta.to.shared.u64 t, %1; cvt.u32.u64 %0, t; }"
        : "=r"(a) : "l"(p));
    return a;
}
__device__ __forceinline__ void ldsm_x4(unsigned addr, unsigned& r0, unsigned& r1,
                                        unsigned& r2, unsigned& r3) {
    asm volatile("ldmatrix.sync.aligned.m8n8.x4.shared.b16 {%0,%1,%2,%3}, [%4];"
                 : "=r"(r0), "=r"(r1), "=r"(r2), "=r"(r3) : "r"(addr));
}
__device__ __forceinline__ void ldsm_x4t(unsigned addr, unsigned& r0, unsigned& r1,
                                         unsigned& r2, unsigned& r3) {
    asm volatile("ldmatrix.sync.aligned.m8n8.x4.trans.shared.b16 {%0,%1,%2,%3}, [%4];"
                 : "=r"(r0), "=r"(r1), "=r"(r2), "=r"(r3) : "r"(addr));
}
__device__ __forceinline__ void mma16816(float& d0, float& d1, float& d2, float& d3,
                                         unsigned a0, unsigned a1, unsigned a2, unsigned a3,
                                         unsigned b0, unsigned b1) {
    asm volatile(
        "mma.sync.aligned.m16n8k16.row.col.f32.f16.f16.f32 "
        "{%0,%1,%2,%3}, {%4,%5,%6,%7}, {%8,%9}, {%0,%1,%2,%3};"
        : "+f"(d0), "+f"(d1), "+f"(d2), "+f"(d3)
        : "r"(a0), "r"(a1), "r"(a2), "r"(a3), "r"(b0), "r"(b1));
}

// ---- prep: pack masked weights into g_w (float view) ----
__global__ void pixelcnn_prep(const float* __restrict__ w1, const float* __restrict__ b1,
                              const float* __restrict__ w2, const float* __restrict__ b2,
                              const float* __restrict__ w3, const float* __restrict__ b3)
{
    float* dst = reinterpret_cast<float*>(&g_w);
    const int tid = threadIdx.x;

    for (int idx = tid; idx < 24 * NCH; idx += 256) {
        int t = idx / NCH, oc = idx % NCH;
        int ky, kx;
        if (t < 21) { ky = t / 7; kx = t % 7; }
        else        { ky = 3;     kx = t - 21; }
        dst[idx] = w1[oc * 49 + ky * 7 + kx];
    }
    for (int idx = tid; idx < NCH * 5 * NCH; idx += 256) {
        int ic  = idx / (5 * NCH);
        int rem = idx % (5 * NCH);
        int t   = rem / NCH;
        int oc  = rem % NCH;
        int ky, kx;
        if (t < 3) { ky = 0; kx = t; }
        else       { ky = 1; kx = t - 3; }
        dst[384 + idx] = w2[((oc * NCH + ic) * 3 + ky) * 3 + kx];
    }
    if (tid < NCH) {
        dst[1664 + tid] = b1[tid];
        dst[1680 + tid] = b2[tid];
        dst[1696 + tid] = w3[tid];
    }
    if (tid == 0) dst[1712] = b3[0];
}

__global__ __launch_bounds__(256, 5)
void pixelcnn_fused(const float* __restrict__ x, float* __restrict__ out)
{
    __shared__ __align__(16) float   sx[XR][XC];        // 3456 B
    __shared__ __align__(16) __half  A[AROWS][16];      // 19072 B (swizzled chunks)
    __shared__ __align__(16) __half  Bh[5][16][16];     // 2560 B
    __shared__ __align__(16) __half  Bl[5][16][16];     // 2560 B

    const int tid  = threadIdx.x;
    const int lane = tid & 31;
    const int wid  = tid >> 5;
    const int img  = blockIdx.y;
    const int r0   = blockIdx.x * TH;
    const float* __restrict__ xim = x + img * (IMG_H * IMG_W);
    const float* cwf = reinterpret_cast<const float*>(&c_w);

    // ---- load x halo tile (zero padded) ----
    for (int idx = tid; idx < XR * XC; idx += 256) {
        int i = idx / XC, j = idx % XC;
        int gr = r0 - 4 + i;
        int gc = j - 4;
        float v = 0.0f;
        if (gr >= 0 && gr < IMG_H && gc >= 0 && gc < IMG_W)
            v = xim[gr * IMG_W + gc];
        sx[i][j] = v;
    }

    // ---- build conv2 B matrices (hi/lo f16 weight split) ----
    for (int idx = tid; idx < 16 * 5 * 16; idx += 256) {
        int ic  = idx / 80;
        int rem = idx % 80;
        int t   = rem / 16;
        int oc  = rem % 16;
        float v = cwf[384 + ic * 80 + t * 16 + oc];
        __half hi = __float2half_rn(v);
        __half lo = __float2half_rn(v - __half2float(hi));
        Bh[t][ic][oc] = hi;
        Bl[t][ic][oc] = lo;
    }

    // ---- zero A pad rows (594, 595) ----
    if (tid < 16) {
        int rr = 594 + (tid >> 3);
        int cc = (tid & 7) * 2;
        *reinterpret_cast<unsigned*>(&A[rr][cc]) = 0u;
    }
    __syncthreads();

    // ---- conv1: 1188 half-pixel tasks (8 oc each), balanced over threads ----
    for (int task = tid; task < 1188; task += 256) {
        const int m  = task >> 1;
        const int h  = task & 1;          // oc half: channels 8h..8h+7
        const int hr = m / 66;
        const int hc = m - hr * 66;
        const int grow = r0 - 1 + hr;
        const bool ok = (grow >= 0) && (hc >= 1) && (hc < 65);

        u64 acc[4];
        #pragma unroll
        for (int q = 0; q < 4; q++) acc[q] = c_w.b1[h * 4 + q];

        #pragma unroll
        for (int ky = 0; ky < 3; ky++) {
            #pragma unroll
            for (int kx = 0; kx < 7; kx++) {
                const int t = ky * 7 + kx;
                const u64 d = dup2(sx[hr + ky][hc + kx]);
                #pragma unroll
                for (int og = 0; og < 2; og++) {
                    ulonglong2 w = c_w.w1t[t][h * 2 + og];
                    acc[og * 2 + 0] = ffma2(w.x, d, acc[og * 2 + 0]);
                    acc[og * 2 + 1] = ffma2(w.y, d, acc[og * 2 + 1]);
                }
            }
        }
        #pragma unroll
        for (int kx = 0; kx < 3; kx++) {
            const int t = 21 + kx;
            const u64 d = dup2(sx[hr + 3][hc + kx]);
            #pragma unroll
            for (int og = 0; og < 2; og++) {
                ulonglong2 w = c_w.w1t[t][h * 2 + og];
                acc[og * 2 + 0] = ffma2(w.x, d, acc[og * 2 + 0]);
                acc[og * 2 + 1] = ffma2(w.y, d, acc[og * 2 + 1]);
            }
        }

        // relu + mask -> fp16, one swizzled STS.128 (16B chunk)
        unsigned hiw[4];
        #pragma unroll
        for (int q = 0; q < 4; q++) {
            float2 v = unpack2(acc[q]);
            float a0 = ok ? fmaxf(v.x, 0.0f) : 0.0f;
            float a1 = ok ? fmaxf(v.y, 0.0f) : 0.0f;
            __half2 hh = __float22half2_rn(make_float2(a0, a1));
            hiw[q] = *reinterpret_cast<unsigned*>(&hh);
        }
        const int s0 = (m >> 2) & 1;   // chunk swizzle: physical = logical ^ s0
        reinterpret_cast<uint4*>(&A[m][0])[h ^ s0] =
            make_uint4(hiw[0], hiw[1], hiw[2], hiw[3]);
    }
    __syncthreads();

    // ---- conv2 via mma (2-term; Bh hoisted, Bl per-tile) + conv3 + sigmoid ----
    {
        const unsigned a_b  = smem_u32(&A[0][0]);
        const unsigned bh_b = smem_u32(&Bh[0][0][0]);
        const unsigned bl_b = smem_u32(&Bl[0][0][0]);

        const unsigned arow  = lane & 15;
        const unsigned akoff = (lane >> 4) * 16;
        const unsigned brow  = lane & 15;
        const unsigned bnoff = (lane >> 4) * 16;
        const unsigned blane = brow * 32 + bnoff;

        // hoist only Bh fragments (20 regs); Bl reloaded per tile
        unsigned bh[5][4];
        #pragma unroll
        for (int t = 0; t < 5; t++) {
            const unsigned bbyte = (unsigned)t * 512 + blane;
            ldsm_x4t(bh_b + bbyte, bh[t][0], bh[t][1], bh[t][2], bh[t][3]);
        }

        // epilogue constants
        const int cb = (lane & 3) * 2;
        float b2c[4], w3c[4];
        #pragma unroll
        for (int j = 0; j < 2; j++) {
            b2c[j]     = cwf[1680 + cb + j];
            b2c[2 + j] = cwf[1680 + cb + 8 + j];
            w3c[j]     = cwf[1696 + cb + j];
            w3c[2 + j] = cwf[1696 + cb + 8 + j];
        }
        const float b3v = cwf[1712];

        const int shifts[5] = {0, 1, 2, 66, 67};

        for (int tile = wid; tile < 33; tile += 8) {
            const int m0 = tile * 16;
            float d0[4] = {0.f, 0.f, 0.f, 0.f};
            float d1[4] = {0.f, 0.f, 0.f, 0.f};

            #pragma unroll
            for (int t = 0; t < 5; t++) {
                const unsigned row   = (unsigned)(m0 + shifts[t]) + arow;
                const unsigned rbyte = row * 32 + (akoff ^ ((row & 4u) << 2));
                unsigned a0, a1, a2, a3;
                ldsm_x4(a_b + rbyte, a0, a1, a2, a3);
                unsigned l0, l1, l2, l3;
                ldsm_x4t(bl_b + (unsigned)t * 512 + blane, l0, l1, l2, l3);

                mma16816(d0[0], d0[1], d0[2], d0[3], a0, a1, a2, a3, bh[t][0], bh[t][1]);
                mma16816(d1[0], d1[1], d1[2], d1[3], a0, a1, a2, a3, bh[t][2], bh[t][3]);
                mma16816(d0[0], d0[1], d0[2], d0[3], a0, a1, a2, a3, l0, l1);
                mma16816(d1[0], d1[1], d1[2], d1[3], a0, a1, a2, a3, l2, l3);
            }

            float zA = 0.f, zB = 0.f;
            #pragma unroll
            for (int j = 0; j < 2; j++) {
                zA += fmaxf(d0[j]     + b2c[j],     0.0f) * w3c[j];
                zA += fmaxf(d1[j]     + b2c[2 + j], 0.0f) * w3c[2 + j];
                zB += fmaxf(d0[2 + j] + b2c[j],     0.0f) * w3c[j];
                zB += fmaxf(d1[2 + j] + b2c[2 + j], 0.0f) * w3c[2 + j];
            }
            zA += __shfl_xor_sync(0xffffffffu, zA, 1);
            zA += __shfl_xor_sync(0xffffffffu, zA, 2);
            zB += __shfl_xor_sync(0xffffffffu, zB, 1);
            zB += __shfl_xor_sync(0xffffffffu, zB, 2);

            if ((lane & 3) == 0) {
                const int g = lane >> 2;
                #pragma unroll
                for (int s = 0; s < 2; s++) {
                    const int m = m0 + g + s * 8;
                    const float z = (s == 0 ? zA : zB) + b3v;
                    const int r = m / 66;
                    const int c = m - r * 66;
                    if (c < 64 && r < 8) {
                        float y = 1.0f / (1.0f + __expf(-z));
                        out[img * (IMG_H * IMG_W) + (r0 + r) * IMG_W + c] = y;
                    }
                }
            }
        }
    }
}

extern "C" void kernel_launch(void* const* d_in, const int* in_sizes, int n_in,
                              void* d_out, int out_size) {
    const float* x  = (const float*)d_in[0];
    const float* w1 = (const float*)d_in[1];
    const float* b1 = (const float*)d_in[2];
    const float* w2 = (const float*)d_in[3];
    const float* b2 = (const float*)d_in[4];
    const float* w3 = (const float*)d_in[5];
    const float* b3 = (const float*)d_in[6];
    float* out = (float*)d_out;

    cudaFuncSetAttribute(pixelcnn_fused,
                         cudaFuncAttributePreferredSharedMemoryCarveout, 100);

    pixelcnn_prep<<<1, 256>>>(w1, b1, w2, b2, w3, b3);

    void* g_addr = nullptr;
    cudaGetSymbolAddress(&g_addr, g_w);
    cudaMemcpyToSymbolAsync(c_w, g_addr, sizeof(PackedW), 0,
                            cudaMemcpyDeviceToDevice, 0);

    dim3 grid(IMG_H / TH, 1024);
    pixelcnn_fused<<<grid, 256>>>(x, out);
}

// round 17
// speedup vs baseline: 1.4150x; 1.4150x over previous
#include <cuda_runtime.h>
#include <cuda_fp16.h>
#include <math.h>

// PixelCNN fused forward.
// R17 = R16 load-balance FIXED: half-tasks ordered [h][m] (h = task>=594),
//       so the oc-half h is WARP-UNIFORM -> constant reads stay broadcast.
//       (R16's h=task&1 made every LDC 2-address divergent: 524us, 3x slower.)
//   conv1 scalar FFMA2 -> A = fp16(relu(h1)), 1188 tasks of 8 oc each;
//   conv2 via mma.m16n8k16: A*Bh + A*Bl (2-term split, rel_err 9.6e-6);
//   XOR 16B-chunk swizzle on A. smem 28KB, 5 CTAs/SM.

#define IMG_H 64
#define IMG_W 64
#define NCH   16
#define TH    8
#define XR    (TH + 4)
#define XC    (IMG_W + 8)
#define AROWS 596          // 9*66 = 594 used + 2 pad

typedef unsigned long long u64;

struct PackedW {
    ulonglong2 w1t[24][4];    // [tap][ocgroup] fp32 pairs
    ulonglong2 w2[16][5][4];  // [ic][tap][ocgroup] fp32
    u64   b1[8];
    u64   b2[8];
    float w3[16];
    float b3;
    float pad[3];
};

__device__   PackedW g_w;
__constant__ PackedW c_w;

__device__ __forceinline__ u64 ffma2(u64 a, u64 b, u64 c) {
    u64 d;
    asm("fma.rn.f32x2 %0, %1, %2, %3;" : "=l"(d) : "l"(a), "l"(b), "l"(c));
    return d;
}
__device__ __forceinline__ u64 dup2(float x) {
    u64 d;
    asm("mov.b64 %0, {%1, %1};" : "=l"(d) : "f"(x));
    return d;
}
__device__ __forceinline__ float2 unpack2(u64 v) {
    float2 r;
    asm("mov.b64 {%0, %1}, %2;" : "=f"(r.x), "=f"(r.y) : "l"(v));
    return r;
}
__device__ __forceinline__ unsigned smem_u32(const void* p) {
    unsigned a;
    asm("{ .reg .u64 t; cvta.to.shared.u64 t, %1; cvt.u32.u64 %0, t; }"
        : "=r"(a) : "l"(p));
    return a;
}
__device__ __forceinline__ void ldsm_x4(unsigned addr, unsigned& r0, unsigned& r1,
                                        unsigned& r2, unsigned& r3) {
    asm volatile("ldmatrix.sync.aligned.m8n8.x4.shared.b16 {%0,%1,%2,%3}, [%4];"
                 : "=r"(r0), "=r"(r1), "=r"(r2), "=r"(r3) : "r"(addr));
}
__device__ __forceinline__ void ldsm_x4t(unsigned addr, unsigned& r0, unsigned& r1,
                                         unsigned& r2, unsigned& r3) {
    asm volatile("ldmatrix.sync.aligned.m8n8.x4.trans.shared.b16 {%0,%1,%2,%3}, [%4];"
                 : "=r"(r0), "=r"(r1), "=r"(r2), "=r"(r3) : "r"(addr));
}
__device__ __forceinline__ void mma16816(float& d0, float& d1, float& d2, float& d3,
                                         unsigned a0, unsigned a1, unsigned a2, unsigned a3,
                                         unsigned b0, unsigned b1) {
    asm volatile(
        "mma.sync.aligned.m16n8k16.row.col.f32.f16.f16.f32 "
        "{%0,%1,%2,%3}, {%4,%5,%6,%7}, {%8,%9}, {%0,%1,%2,%3};"
        : "+f"(d0), "+f"(d1), "+f"(d2), "+f"(d3)
        : "r"(a0), "r"(a1), "r"(a2), "r"(a3), "r"(b0), "r"(b1));
}

// ---- prep: pack masked weights into g_w (float view) ----
__global__ void pixelcnn_prep(const float* __restrict__ w1, const float* __restrict__ b1,
                              const float* __restrict__ w2, const float* __restrict__ b2,
                              const float* __restrict__ w3, const float* __restrict__ b3)
{
    float* dst = reinterpret_cast<float*>(&g_w);
    const int tid = threadIdx.x;

    for (int idx = tid; idx < 24 * NCH; idx += 256) {
        int t = idx / NCH, oc = idx % NCH;
        int ky, kx;
        if (t < 21) { ky = t / 7; kx = t % 7; }
        else        { ky = 3;     kx = t - 21; }
        dst[idx] = w1[oc * 49 + ky * 7 + kx];
    }
    for (int idx = tid; idx < NCH * 5 * NCH; idx += 256) {
        int ic  = idx / (5 * NCH);
        int rem = idx % (5 * NCH);
        int t   = rem / NCH;
        int oc  = rem % NCH;
        int ky, kx;
        if (t < 3) { ky = 0; kx = t; }
        else       { ky = 1; kx = t - 3; }
        dst[384 + idx] = w2[((oc * NCH + ic) * 3 + ky) * 3 + kx];
    }
    if (tid < NCH) {
        dst[1664 + tid] = b1[tid];
        dst[1680 + tid] = b2[tid];
        dst[1696 + tid] = w3[tid];
    }
    if (tid == 0) dst[1712] = b3[0];
}

__global__ __launch_bounds__(256, 5)
void pixelcnn_fused(const float* __restrict__ x, float* __restrict__ out)
{
    __shared__ __align__(16) float   sx[XR][XC];        // 3456 B
    __shared__ __align__(16) __half  A[AROWS][16];      // 19072 B (swizzled chunks)
    __shared__ __align__(16) __half  Bh[5][16][16];     // 2560 B
    __shared__ __align__(16) __half  Bl[5][16][16];     // 2560 B

    const int tid  = threadIdx.x;
    const int lane = tid & 31;
    const int wid  = tid >> 5;
    const int img  = blockIdx.y;
    const int r0   = blockIdx.x * TH;
    const float* __restrict__ xim = x + img * (IMG_H * IMG_W);
    const float* cwf = reinterpret_cast<const float*>(&c_w);

    // ---- load x halo tile (zero padded) ----
    for (int idx = tid; idx < XR * XC; idx += 256) {
        int i = idx / XC, j = idx % XC;
        int gr = r0 - 4 + i;
        int gc = j - 4;
        float v = 0.0f;
        if (gr >= 0 && gr < IMG_H && gc >= 0 && gc < IMG_W)
            v = xim[gr * IMG_W + gc];
        sx[i][j] = v;
    }

    // ---- build conv2 B matrices (hi/lo f16 weight split) ----
    for (int idx = tid; idx < 16 * 5 * 16; idx += 256) {
        int ic  = idx / 80;
        int rem = idx % 80;
        int t   = rem / 16;
        int oc  = rem % 16;
        float v = cwf[384 + ic * 80 + t * 16 + oc];
        __half hi = __float2half_rn(v);
        __half lo = __float2half_rn(v - __half2float(hi));
        Bh[t][ic][oc] = hi;
        Bl[t][ic][oc] = lo;
    }

    // ---- zero A pad rows (594, 595) ----
    if (tid < 16) {
        int rr = 594 + (tid >> 3);
        int cc = (tid & 7) * 2;
        *reinterpret_cast<unsigned*>(&A[rr][cc]) = 0u;
    }
    __syncthreads();

    // ---- conv1: 1188 half-pixel tasks, [h][m] order (h warp-uniform) ----
    for (int task = tid; task < 1188; task += 256) {
        const int h  = (task >= 594) ? 1 : 0;   // oc half: channels 8h..8h+7
        const int m  = task - h * 594;
        const int hr = m / 66;
        const int hc = m - hr * 66;
        const int grow = r0 - 1 + hr;
        const bool ok = (grow >= 0) && (hc >= 1) && (hc < 65);

        u64 acc[4];
        #pragma unroll
        for (int q = 0; q < 4; q++) acc[q] = c_w.b1[h * 4 + q];

        #pragma unroll
        for (int ky = 0; ky < 3; ky++) {
            #pragma unroll
            for (int kx = 0; kx < 7; kx++) {
                const int t = ky * 7 + kx;
                const u64 d = dup2(sx[hr + ky][hc + kx]);
                #pragma unroll
                for (int og = 0; og < 2; og++) {
                    ulonglong2 w = c_w.w1t[t][h * 2 + og];
                    acc[og * 2 + 0] = ffma2(w.x, d, acc[og * 2 + 0]);
                    acc[og * 2 + 1] = ffma2(w.y, d, acc[og * 2 + 1]);
                }
            }
        }
        #pragma unroll
        for (int kx = 0; kx < 3; kx++) {
            const int t = 21 + kx;
            const u64 d = dup2(sx[hr + 3][hc + kx]);
            #pragma unroll
            for (int og = 0; og < 2; og++) {
                ulonglong2 w = c_w.w1t[t][h * 2 + og];
                acc[og * 2 + 0] = ffma2(w.x, d, acc[og * 2 + 0]);
                acc[og * 2 + 1] = ffma2(w.y, d, acc[og * 2 + 1]);
            }
        }

        // relu + mask -> fp16, one swizzled STS.128 (16B chunk)
        unsigned hiw[4];
        #pragma unroll
        for (int q = 0; q < 4; q++) {
            float2 v = unpack2(acc[q]);
            float a0 = ok ? fmaxf(v.x, 0.0f) : 0.0f;
            float a1 = ok ? fmaxf(v.y, 0.0f) : 0.0f;
            __half2 hh = __float22half2_rn(make_float2(a0, a1));
            hiw[q] = *reinterpret_cast<unsigned*>(&hh);
        }
        const int s0 = (m >> 2) & 1;   // chunk swizzle: physical = logical ^ s0
        reinterpret_cast<uint4*>(&A[m][0])[h ^ s0] =
            make_uint4(hiw[0], hiw[1], hiw[2], hiw[3]);
    }
    __syncthreads();

    // ---- conv2 via mma (2-term; Bh hoisted, Bl per-tile) + conv3 + sigmoid ----
    {
        const unsigned a_b  = smem_u32(&A[0][0]);
        const unsigned bh_b = smem_u32(&Bh[0][0][0]);
        const unsigned bl_b = smem_u32(&Bl[0][0][0]);

        const unsigned arow  = lane & 15;
        const unsigned akoff = (lane >> 4) * 16;
        const unsigned brow  = lane & 15;
        const unsigned bnoff = (lane >> 4) * 16;
        const unsigned blane = brow * 32 + bnoff;

        // hoist only Bh fragments (20 regs); Bl reloaded per tile
        unsigned bh[5][4];
        #pragma unroll
        for (int t = 0; t < 5; t++) {
            const unsigned bbyte = (unsigned)t * 512 + blane;
            ldsm_x4t(bh_b + bbyte, bh[t][0], bh[t][1], bh[t][2], bh[t][3]);
        }

        // epilogue constants
        const int cb = (lane & 3) * 2;
        float b2c[4], w3c[4];
        #pragma unroll
        for (int j = 0; j < 2; j++) {
            b2c[j]     = cwf[1680 + cb + j];
            b2c[2 + j] = cwf[1680 + cb + 8 + j];
            w3c[j]     = cwf[1696 + cb + j];
            w3c[2 + j] = cwf[1696 + cb + 8 + j];
        }
        const float b3v = cwf[1712];

        const int shifts[5] = {0, 1, 2, 66, 67};

        for (int tile = wid; tile < 33; tile += 8) {
            const int m0 = tile * 16;
            float d0[4] = {0.f, 0.f, 0.f, 0.f};
            float d1[4] = {0.f, 0.f, 0.f, 0.f};

            #pragma unroll
            for (int t = 0; t < 5; t++) {
                const unsigned row   = (unsigned)(m0 + shifts[t]) + arow;
                const unsigned rbyte = row * 32 + (akoff ^ ((row & 4u) << 2));
                unsigned a0, a1, a2, a3;
                ldsm_x4(a_b + rbyte, a0, a1, a2, a3);
                unsigned l0, l1, l2, l3;
                ldsm_x4t(bl_b + (unsigned)t * 512 + blane, l0, l1, l2, l3);

                mma16816(d0[0], d0[1], d0[2], d0[3], a0, a1, a2, a3, bh[t][0], bh[t][1]);
                mma16816(d1[0], d1[1], d1[2], d1[3], a0, a1, a2, a3, bh[t][2], bh[t][3]);
                mma16816(d0[0], d0[1], d0[2], d0[3], a0, a1, a2, a3, l0, l1);
                mma16816(d1[0], d1[1], d1[2], d1[3], a0, a1, a2, a3, l2, l3);
            }

            float zA = 0.f, zB = 0.f;
            #pragma unroll
            for (int j = 0; j < 2; j++) {
                zA += fmaxf(d0[j]     + b2c[j],     0.0f) * w3c[j];
                zA += fmaxf(d1[j]     + b2c[2 + j], 0.0f) * w3c[2 + j];
                zB += fmaxf(d0[2 + j] + b2c[j],     0.0f) * w3c[j];
                zB += fmaxf(d1[2 + j] + b2c[2 + j], 0.0f) * w3c[2 + j];
            }
            zA += __shfl_xor_sync(0xffffffffu, zA, 1);
            zA += __shfl_xor_sync(0xffffffffu, zA, 2);
            zB += __shfl_xor_sync(0xffffffffu, zB, 1);
            zB += __shfl_xor_sync(0xffffffffu, zB, 2);

            if ((lane & 3) == 0) {
                const int g = lane >> 2;
                #pragma unroll
                for (int s = 0; s < 2; s++) {
                    const int m = m0 + g + s * 8;
                    const float z = (s == 0 ? zA : zB) + b3v;
                    const int r = m / 66;
                    const int c = m - r * 66;
                    if (c < 64 && r < 8) {
                        float y = 1.0f / (1.0f + __expf(-z));
                        out[img * (IMG_H * IMG_W) + (r0 + r) * IMG_W + c] = y;
                    }
                }
            }
        }
    }
}

extern "C" void kernel_launch(void* const* d_in, const int* in_sizes, int n_in,
                              void* d_out, int out_size) {
    const float* x  = (const float*)d_in[0];
    const float* w1 = (const float*)d_in[1];
    const float* b1 = (const float*)d_in[2];
    const float* w2 = (const float*)d_in[3];
    const float* b2 = (const float*)d_in[4];
    const float* w3 = (const float*)d_in[5];
    const float* b3 = (const float*)d_in[6];
    float* out = (float*)d_out;

    cudaFuncSetAttribute(pixelcnn_fused,
                         cudaFuncAttributePreferredSharedMemoryCarveout, 100);

    pixelcnn_prep<<<1, 256>>>(w1, b1, w2, b2, w3, b3);

    void* g_addr = nullptr;
    cudaGetSymbolAddress(&g_addr, g_w);
    cudaMemcpyToSymbolAsync(c_w, g_addr, sizeof(PackedW), 0,
                            cudaMemcpyDeviceToDevice, 0);

    dim3 grid(IMG_H / TH, 1024);
    pixelcnn_fused<<<grid, 256>>>(x, out);
}